// round 1
// baseline (speedup 1.0000x reference)
#include <cuda_runtime.h>

#define CIN  64
#define HH   32
#define WW   32
#define COUT 128
#define NK   9

// Pre-scale factor: (1/(2*N_IDEAL*VT)) * log2(e) = 13.3333333 * 1.4426950
#define PSCALE   19.235933878f
// 15 * log2(e): skip/clamp threshold in base-2 z units
#define ZCLAMP   21.640425f
// exp(-shift) = exp(-4/3)
#define CEXP     0.26359713812f
// ln(2)^2
#define LN2SQ    0.48045301392f
// 2*s*ln2 = 2*(4/3)*ln2
#define TWOSLN2  1.84839248151f
// s^2
#define SSQ      1.77777778f
// ALPHA * R
#define OSCALE   5.625e-5f

__device__ float g_thT[CIN * NK * COUT];  // [cin*9+kk][co], scaled by PSCALE

__device__ __forceinline__ float ex2a(float x) {
    float r; asm("ex2.approx.ftz.f32 %0, %1;" : "=f"(r) : "f"(x)); return r;
}
__device__ __forceinline__ float lg2a(float x) {
    float r; asm("lg2.approx.ftz.f32 %0, %1;" : "=f"(r) : "f"(x)); return r;
}

__global__ void k_transpose(const float* __restrict__ theta) {
    int i = blockIdx.x * 256 + threadIdx.x;
    if (i < CIN * NK * COUT) {
        int co = i / (CIN * NK);      // theta layout: [co][cin][kk]
        int r  = i % (CIN * NK);
        g_thT[r * COUT + co] = theta[i] * PSCALE;
    }
}

__global__ void __launch_bounds__(128)
k_main(const float* __restrict__ x, float* __restrict__ out) {
    extern __shared__ float sm[];
    float* s_x   = sm;                 // [CIN][6][34], x * PSCALE, zero-padded
    float* s_xmt = sm + CIN * 204;     // [4 warps][CIN]: warp-window max + ZCLAMP

    const int tid  = threadIdx.x;
    const int w    = tid >> 5;         // warp = output row within 4-row tile
    const int lane = tid & 31;         // lane = output column
    const int r0   = blockIdx.x << 2;  // row tile base (8 tiles * 4 rows = 32)
    const int b    = blockIdx.y;       // batch
    const int co0  = blockIdx.z << 5;  // co group of 32

    // ---- load padded, pre-scaled x tile into smem ----
    const float* xb = x + b * (CIN * HH * WW);
    for (int idx = tid; idx < CIN * 204; idx += 128) {
        int cin = idx / 204;
        int rem = idx - cin * 204;
        int rr  = rem / 34;
        int cc  = rem - rr * 34;
        int gr  = r0 - 1 + rr;
        int gc  = cc - 1;
        float v = 0.f;
        if ((unsigned)gr < HH && (unsigned)gc < WW)
            v = xb[cin * (HH * WW) + gr * WW + gc] * PSCALE;
        s_x[idx] = v;
    }
    __syncthreads();

    // ---- per-warp, per-cin conservative x-window max (for uniform skip test) ----
    for (int cin = 0; cin < CIN; ++cin) {
        const float* p = s_x + cin * 204 + w * 34;
        float m = fmaxf(fmaxf(p[lane], p[lane + 34]), p[lane + 68]);
        if (lane < 2)  // cols 32,33 of the 34-wide padded window
            m = fmaxf(m, fmaxf(fmaxf(p[32 + lane], p[66 + lane]), p[100 + lane]));
        #pragma unroll
        for (int off = 16; off; off >>= 1)
            m = fmaxf(m, __shfl_xor_sync(0xffffffffu, m, off));
        if (lane == 0) s_xmt[w * CIN + cin] = m + ZCLAMP;
    }
    __syncthreads();

    // ---- main compute: 2 chunks of 16 output channels ----
    #pragma unroll 1
    for (int half = 0; half < 2; ++half) {
        const int cob = co0 + half * 16;
        float acc[16];
        #pragma unroll
        for (int j = 0; j < 16; ++j) acc[j] = 0.f;

        #pragma unroll 1
        for (int cin = 0; cin < CIN; ++cin) {
            const float xmt = s_xmt[w * CIN + cin];           // warp-uniform
            const float* xr = s_x + cin * 204 + w * 34 + lane;
            const float* th = g_thT + cin * (NK * COUT) + cob;
            #pragma unroll 1
            for (int di = 0; di < 3; ++di) {
                #pragma unroll 1
                for (int dj = 0; dj < 3; ++dj) {
                    const float xv = xr[di * 34 + dj];
                    const float* thk = th + (di * 3 + dj) * COUT;
                    #pragma unroll
                    for (int j = 0; j < 16; ++j) {
                        float t = __ldg(thk + j);             // warp-uniform broadcast
                        if (t < xmt) {                        // uniform: max z >= -15
                            float z  = xv - t;                // z2 = z/ln2 units
                            float e  = ex2a(fminf(z, ZCLAMP));
                            float l1 = lg2a(1.f + e);
                            float l2 = lg2a(fmaf(e, CEXP, 1.f));
                            float g  = (l1 - l2) * (l1 + l2); // softplus^2 diff / ln2^2
                            float fl = fmaf(TWOSLN2, z, -SSQ); // exact linear tail
                            acc[j] += (z > ZCLAMP) ? fl : g * LN2SQ;
                        }
                    }
                }
            }
        }

        float* op = out + (b * COUT + cob) * 1024 + (r0 + w) * 32 + lane;
        #pragma unroll
        for (int j = 0; j < 16; ++j)
            op[j * 1024] = fminf(fmaxf(acc[j] * OSCALE, 0.f), 9.f);
    }
}

extern "C" void kernel_launch(void* const* d_in, const int* in_sizes, int n_in,
                              void* d_out, int out_size) {
    const float* xin   = (const float*)d_in[0];
    const float* theta = (const float*)d_in[1];
    // defensive: metadata order should be (input_voltage, theta); swap if reversed
    if (n_in >= 2 && in_sizes[0] == CIN * NK * COUT) {
        const float* t = xin; xin = theta; theta = t;
    }

    const int smem_bytes = (CIN * 204 + 4 * CIN) * 4;  // 53,248 B
    cudaFuncSetAttribute(k_main, cudaFuncAttributeMaxDynamicSharedMemorySize, smem_bytes);

    k_transpose<<<(CIN * NK * COUT + 255) / 256, 256>>>(theta);

    dim3 grid(8, 32, 4);  // row tiles, batch, co groups
    k_main<<<grid, 128, smem_bytes>>>(xin, (float*)d_out);
}

// round 2
// speedup vs baseline: 1.2046x; 1.2046x over previous
#include <cuda_runtime.h>

#define CIN  64
#define HH   32
#define WW   32
#define COUT 128
#define NK   9

// (1/(2*N_IDEAL*VT)) * log2(e) = 13.3333333 * 1.4426950
#define PSCALE   19.235933878f
// 15 * log2(e)
#define ZCLAMP   21.640425f
// exp(-4/3)
#define CEXP     0.26359713812f
// ln(2)^2
#define LN2SQ    0.48045301392f
// 2*(4/3)*ln2
#define TWOSLN2  1.84839248151f
// (4/3)^2
#define SSQ      1.77777778f
// ALPHA * R
#define OSCALE   5.625e-5f

// Sorted theta: 256 bins = (cin, co-group). Each bin: 288 elements as float2
// {theta_scaled, packed(tap_off | co_local<<16)}, ascending by theta.
// 288 float2 = 144 float4 per bin. +2 float4 pad for unconditional prefetch.
__device__ float4 g_sorted4[256 * 72 * 2 + 2];

__device__ __forceinline__ float ex2a(float x) {
    float r; asm("ex2.approx.ftz.f32 %0, %1;" : "=f"(r) : "f"(x)); return r;
}
__device__ __forceinline__ float lg2a(float x) {
    float r; asm("lg2.approx.ftz.f32 %0, %1;" : "=f"(r) : "f"(x)); return r;
}

// ---------------- prepass: per-(cin, co-group) bitonic sort of 288 thetas ----------------
__global__ void __launch_bounds__(512) k_sort(const float* __restrict__ theta) {
    __shared__ float sk[512];
    __shared__ unsigned sv[512];
    const int bx  = blockIdx.x;          // 256 bins
    const int cin = bx >> 2;
    const int grp = bx & 3;
    const int t   = threadIdx.x;

    float key = 1e30f;
    unsigned val = 0;
    if (t < 288) {
        int co_l = t / 9;
        int kk   = t - co_l * 9;
        int co   = grp * 32 + co_l;
        key = theta[(co * CIN + cin) * NK + kk] * PSCALE;
        val = ((unsigned)co_l << 16) | (unsigned)((kk / 3) * 34 + (kk % 3));
    }
    sk[t] = key; sv[t] = val;
    __syncthreads();

    for (int ksz = 2; ksz <= 512; ksz <<= 1) {
        for (int j = ksz >> 1; j > 0; j >>= 1) {
            int ixj = t ^ j;
            if (ixj > t) {
                bool up = ((t & ksz) == 0);
                float a = sk[t], b = sk[ixj];
                if (up ? (a > b) : (a < b)) {
                    unsigned va = sv[t], vb = sv[ixj];
                    sk[t] = b; sk[ixj] = a;
                    sv[t] = vb; sv[ixj] = va;
                }
            }
            __syncthreads();
        }
    }

    if (t < 288) {
        float2* dst = (float2*)g_sorted4;
        dst[bx * 288 + t] = make_float2(sk[t], __uint_as_float(sv[t]));
    }
}

// ---------------- main kernel ----------------
__device__ __forceinline__ void proc_elem(float t, float pv, bool live,
                                          const float* __restrict__ xb,
                                          float* __restrict__ acc_t) {
    unsigned pk = __float_as_uint(pv);
    int off = pk & 0xffff;
    int co  = pk >> 16;
    float xv = xb[off];                       // LDS, conflict-free
    float z  = xv - t;                        // base-2 units
    float e  = ex2a(fminf(z, ZCLAMP));
    float l1 = lg2a(1.f + e);
    float l2 = lg2a(fmaf(e, CEXP, 1.f));
    float g  = (l1 - l2) * (l1 + l2) * LN2SQ;
    float r  = (z > ZCLAMP) ? fmaf(TWOSLN2, z, -SSQ) : g;
    float* a = acc_t + (co << 7);
    float old = *a;
    if (live) *a = old + r;                   // predicated STS only
}

__global__ void __launch_bounds__(128)
k_main(const float* __restrict__ x, float* __restrict__ out) {
    extern __shared__ float sm[];
    float* s_x   = sm;                        // [CIN][6][34] scaled, padded
    float* s_acc = sm + CIN * 204;            // [32 co][128 tid]
    float* s_xmt = s_acc + 32 * 128;          // [4 warps][CIN]

    const int tid  = threadIdx.x;
    const int w    = tid >> 5;
    const int lane = tid & 31;
    const int r0   = blockIdx.x << 2;         // 8 row tiles * 4 rows
    const int b    = blockIdx.y;
    const int grp  = blockIdx.z;              // co group of 32

    // ---- x tile -> smem (scaled, zero-padded) ----
    const float* xbase = x + b * (CIN * HH * WW);
    for (int idx = tid; idx < CIN * 204; idx += 128) {
        int cin = idx / 204;
        int rem = idx - cin * 204;
        int rr  = rem / 34;
        int cc  = rem - rr * 34;
        int gr  = r0 - 1 + rr;
        int gc  = cc - 1;
        float v = 0.f;
        if ((unsigned)gr < HH && (unsigned)gc < WW)
            v = xbase[cin * (HH * WW) + gr * WW + gc] * PSCALE;
        s_x[idx] = v;
    }
    // zero this thread's private accumulator slots (only this thread touches them)
    #pragma unroll
    for (int c = 0; c < 32; ++c) s_acc[(c << 7) + tid] = 0.f;
    __syncthreads();

    // ---- per-(warp,cin) window max threshold ----
    for (int cin = 0; cin < CIN; ++cin) {
        const float* p = s_x + cin * 204 + w * 34;
        float m = fmaxf(fmaxf(p[lane], p[lane + 34]), p[lane + 68]);
        if (lane < 2)
            m = fmaxf(m, fmaxf(fmaxf(p[32 + lane], p[66 + lane]), p[100 + lane]));
        #pragma unroll
        for (int off = 16; off; off >>= 1)
            m = fmaxf(m, __shfl_xor_sync(0xffffffffu, m, off));
        if (lane == 0) s_xmt[w * CIN + cin] = m + ZCLAMP;
    }
    __syncthreads();

    float* acc_t = s_acc + tid;

    // ---- dense walk over sorted-live elements ----
    #pragma unroll 1
    for (int cin = 0; cin < CIN; ++cin) {
        const float  xmt = s_xmt[w * CIN + cin];
        const float* xb  = s_x + cin * 204 + w * 34 + lane;
        const float4* pp = g_sorted4 + (cin * 4 + grp) * 72 * 2;

        float4 A = __ldg(pp);
        float4 B = __ldg(pp + 1);
        #pragma unroll 1
        for (int i = 0; i < 144; i += 2) {
            if (A.x >= xmt) break;                     // warp-uniform: rest are dead
            float4 A2 = __ldg(pp + i + 2);             // unconditional prefetch (padded)
            float4 B2 = __ldg(pp + i + 3);
            proc_elem(A.x, A.y, true,        xb, acc_t);
            proc_elem(A.z, A.w, A.z < xmt,   xb, acc_t);
            proc_elem(B.x, B.y, B.x < xmt,   xb, acc_t);
            proc_elem(B.z, B.w, B.z < xmt,   xb, acc_t);
            A = A2; B = B2;
        }
    }

    // ---- epilogue: scale, clip, store (this thread's private slots; no sync needed) ----
    float* op = out + ((long)b * COUT + grp * 32) * 1024 + (r0 + w) * 32 + lane;
    #pragma unroll
    for (int c = 0; c < 32; ++c) {
        float v = s_acc[(c << 7) + tid] * OSCALE;
        op[c * 1024] = fminf(fmaxf(v, 0.f), 9.f);
    }
}

extern "C" void kernel_launch(void* const* d_in, const int* in_sizes, int n_in,
                              void* d_out, int out_size) {
    const float* xin   = (const float*)d_in[0];
    const float* theta = (const float*)d_in[1];
    if (n_in >= 2 && in_sizes[0] == CIN * NK * COUT) {  // defensive swap
        const float* t = xin; xin = theta; theta = t;
    }

    const int smem_bytes = (CIN * 204 + 32 * 128 + 4 * CIN) * 4;  // 69,632 B
    cudaFuncSetAttribute(k_main, cudaFuncAttributeMaxDynamicSharedMemorySize, smem_bytes);

    k_sort<<<256, 512>>>(theta);

    dim3 grid(8, 32, 4);
    k_main<<<grid, 128, smem_bytes>>>(xin, (float*)d_out);
}

// round 3
// speedup vs baseline: 3.0098x; 2.4986x over previous
#include <cuda_runtime.h>

#define CIN  64
#define HH   32
#define WW   32
#define COUT 128
#define NK   9

// (1/(2*N_IDEAL*VT)) * log2(e)
#define PSCALE   19.235933878f
// skip threshold in base-2 z units (~5.5 nats): contributions below ~2^-16
#define TSKIP    8.0f
// clamp for ex2 arg / linear-tail switch: 15*log2(e)
#define ZCLAMP   21.640425f
// exp(-4/3) = 2^(-s_b2)
#define CEXP     0.26359713812f
// s in base-2 units: (4/3)*log2(e)
#define B2LIN    3.8471867757f   // 2*s_b2
#define B2SQ     3.7002114715f   // s_b2^2
// ALPHA * R * ln(2)^2  (accumulate in log2^2 units)
#define OSCALE_EFF 2.7025482e-5f

// Sorted theta: 256 bins = (cin, co-group-of-32). 288 float2 {theta_scaled,
// packed} ascending by theta = 144 float4 per bin. packed = (co_l<<25) |
// (byte offset of tap within 16-cin x tile). +4 float4 pad for prefetch.
__device__ float4 g_sorted4[256 * 144 + 4];

__device__ __forceinline__ float ex2a(float x) {
    float r; asm("ex2.approx.ftz.f32 %0, %1;" : "=f"(r) : "f"(x)); return r;
}
__device__ __forceinline__ float lg2a(float x) {
    float r; asm("lg2.approx.ftz.f32 %0, %1;" : "=f"(r) : "f"(x)); return r;
}

// ---------------- prepass: per-(cin, co-group) bitonic sort of 288 thetas ----------------
__global__ void __launch_bounds__(512) k_sort(const float* __restrict__ theta) {
    __shared__ float sk[512];
    __shared__ unsigned sv[512];
    const int bx  = blockIdx.x;          // 256 bins = cin*4 + grp
    const int cin = bx >> 2;
    const int grp = bx & 3;
    const int t   = threadIdx.x;

    float key = 1e30f;
    unsigned val = 0;
    if (t < 288) {
        int co_l = t / 9;
        int kk   = t - co_l * 9;
        int co   = grp * 32 + co_l;
        key = theta[(co * CIN + cin) * NK + kk] * PSCALE;
        // tap byte offset inside the 16-cin phase tile [16][6][34] f32
        unsigned off = ((unsigned)(cin & 15) * 204 + (kk / 3) * 34 + (kk % 3)) * 4u;
        val = ((unsigned)co_l << 25) | off;   // pk>>16 = co_l*512 = acc byte stride
    }
    sk[t] = key; sv[t] = val;
    __syncthreads();

    for (int ksz = 2; ksz <= 512; ksz <<= 1) {
        for (int j = ksz >> 1; j > 0; j >>= 1) {
            int ixj = t ^ j;
            if (ixj > t) {
                bool up = ((t & ksz) == 0);
                float a = sk[t], b = sk[ixj];
                if (up ? (a > b) : (a < b)) {
                    unsigned va = sv[t], vb = sv[ixj];
                    sk[t] = b; sk[ixj] = a;
                    sv[t] = vb; sv[ixj] = va;
                }
            }
            __syncthreads();
        }
    }

    if (t < 288) {
        float2* dst = (float2*)g_sorted4;
        dst[bx * 288 + t] = make_float2(sk[t], __uint_as_float(sv[t]));
    }
}

// ---------------- main kernel ----------------
__device__ __forceinline__ void proc_elem(float t, float pv,
                                          const char* __restrict__ xc,
                                          char* __restrict__ accc) {
    unsigned pk = __float_as_uint(pv);
    float xv = *(const float*)(xc + (pk & 0xffffu));   // LDS, conflict-free
    float z  = xv - t;                                  // base-2 units
    float e  = ex2a(fminf(z, ZCLAMP));
    float l1 = lg2a(1.f + e);
    float l2 = lg2a(fmaf(e, CEXP, 1.f));
    float g  = (l1 - l2) * (l1 + l2);
    float r  = (z > ZCLAMP) ? fmaf(B2LIN, z, -B2SQ) : g;
    float* a = (float*)(accc + (pk >> 16));            // private slot
    *a += r;
}

__global__ void __launch_bounds__(128)
k_main(const float* __restrict__ x, float* __restrict__ out) {
    extern __shared__ float sm[];
    float* s_x   = sm;                 // [16][6][34] scaled, padded (one phase)
    float* s_acc = sm + 16 * 204;      // [32 co][128 tid]
    float* s_xmt = s_acc + 32 * 128;   // [4 warps][16 cin_local]

    const int tid  = threadIdx.x;
    const int w    = tid >> 5;
    const int lane = tid & 31;
    const int r0   = blockIdx.x << 2;  // 8 row tiles * 4 rows
    const int b    = blockIdx.y;
    const int grp  = blockIdx.z;       // co group of 32

    // private accumulator slots (each slot read/written by exactly one thread)
    #pragma unroll
    for (int c = 0; c < 32; ++c) s_acc[(c << 7) + tid] = 0.f;

    const float* xbase = x + b * (CIN * HH * WW);
    const char*  xc    = (const char*)(s_x + w * 34 + lane);
    char*        accc  = (char*)(s_acc + tid);

    #pragma unroll 1
    for (int ph = 0; ph < 4; ++ph) {
        const int cb = ph << 4;        // cin base of this phase

        __syncthreads();               // previous phase done reading s_x
        for (int idx = tid; idx < 16 * 204; idx += 128) {
            int cl  = idx / 204;
            int rem = idx - cl * 204;
            int rr  = rem / 34;
            int cc  = rem - rr * 34;
            int gr  = r0 - 1 + rr;
            int gc  = cc - 1;
            float v = 0.f;
            if ((unsigned)gr < HH && (unsigned)gc < WW)
                v = xbase[(cb + cl) * (HH * WW) + gr * WW + gc] * PSCALE;
            s_x[idx] = v;
        }
        __syncthreads();

        // per-(warp, cin_local) window max + TSKIP  (warp-private)
        for (int cl = 0; cl < 16; ++cl) {
            const float* p = s_x + cl * 204 + w * 34;
            float m = fmaxf(fmaxf(p[lane], p[lane + 34]), p[lane + 68]);
            if (lane < 2)
                m = fmaxf(m, fmaxf(fmaxf(p[32 + lane], p[66 + lane]), p[100 + lane]));
            #pragma unroll
            for (int off = 16; off; off >>= 1)
                m = fmaxf(m, __shfl_xor_sync(0xffffffffu, m, off));
            if (lane == 0) s_xmt[w * 16 + cl] = m + TSKIP;
        }
        __syncwarp();

        // dense walk over sorted-live elements of the 16 bins of this phase
        #pragma unroll 1
        for (int cl = 0; cl < 16; ++cl) {
            const float   xmt = s_xmt[w * 16 + cl];
            const float4* pp  = g_sorted4 + ((cb + cl) * 4 + grp) * 144;

            float4 A = __ldg(pp);
            float4 B = __ldg(pp + 1);
            #pragma unroll 1
            for (int i = 0; i < 144; i += 2) {
                if (A.x >= xmt) break;            // warp-uniform: rest are dead
                float4 A2 = __ldg(pp + i + 2);    // unconditional prefetch (padded)
                float4 B2 = __ldg(pp + i + 3);
                proc_elem(A.x, A.y, xc, accc);
                proc_elem(A.z, A.w, xc, accc);
                proc_elem(B.x, B.y, xc, accc);
                proc_elem(B.z, B.w, xc, accc);
                A = A2; B = B2;
            }
        }
    }

    // epilogue: scale, clip, store (own slots only; no sync needed)
    float* op = out + ((long)b * COUT + grp * 32) * 1024 + (r0 + w) * 32 + lane;
    #pragma unroll
    for (int c = 0; c < 32; ++c) {
        float v = s_acc[(c << 7) + tid] * OSCALE_EFF;
        op[c * 1024] = fminf(fmaxf(v, 0.f), 9.f);
    }
}

extern "C" void kernel_launch(void* const* d_in, const int* in_sizes, int n_in,
                              void* d_out, int out_size) {
    const float* xin   = (const float*)d_in[0];
    const float* theta = (const float*)d_in[1];
    if (n_in >= 2 && in_sizes[0] == CIN * NK * COUT) {  // defensive swap
        const float* t = xin; xin = theta; theta = t;
    }

    const int smem_bytes = (16 * 204 + 32 * 128 + 4 * 16) * 4;  // 29,952 B
    cudaFuncSetAttribute(k_main, cudaFuncAttributeMaxDynamicSharedMemorySize, smem_bytes);

    k_sort<<<256, 512>>>(theta);

    dim3 grid(8, 32, 4);
    k_main<<<grid, 128, smem_bytes>>>(xin, (float*)d_out);
}